// round 1
// baseline (speedup 1.0000x reference)
#include <cuda_runtime.h>
#include <math.h>

#define DIM   512
#define LBLK  64
#define NHEAD 8
#define HDIM  64
#define KEYS  65
#define BB    2
#define NTOK  32768
#define NBPB  512                 // blocks per batch
#define NBLK  (BB*NBPB)           // 1024
#define MTOK  (BB*NTOK)           // 65536
#define MAUG  (MTOK+NBLK)         // 66560
#define QKVN  (3*DIM)             // 1536

// ---------------- scratch (device globals; no runtime allocation) ----------
__device__ float g_blocknode[(size_t)NBLK * DIM];                 // 2 MB
__device__ float g_yqkv[(size_t)MAUG * QKVN];                     // ~409 MB
__device__ float g_attnout[(size_t)MTOK * DIM];                   // 134 MB

// ---------------- kernel 1: per-block mean over L=64 rows ------------------
__global__ void block_mean_kernel(const float* __restrict__ x) {
    int blk = blockIdx.x;           // 0..NBLK-1
    int c4  = threadIdx.x;          // 0..127 (float4 index over C=512)
    const float4* xr = (const float4*)x + (size_t)blk * LBLK * (DIM / 4) + c4;
    float4 acc = make_float4(0.f, 0.f, 0.f, 0.f);
#pragma unroll 4
    for (int r = 0; r < LBLK; r++) {
        float4 v = xr[(size_t)r * (DIM / 4)];
        acc.x += v.x; acc.y += v.y; acc.z += v.z; acc.w += v.w;
    }
    const float s = 1.f / 64.f;
    acc.x *= s; acc.y *= s; acc.z *= s; acc.w *= s;
    ((float4*)g_blocknode)[(size_t)blk * (DIM / 4) + c4] = acc;
}

// ---------------- generic SGEMM: C[M,N] = A[M,K] @ W[N,K]^T + bias[N] ------
// A rows come from A0 for row-tiles < splitTiles, else from A1 (block nodes).
#define BM 128
#define BN 128
#define BKK 16
#define TM 8
#define TN 8

__global__ __launch_bounds__(256) void sgemm_bias_kernel(
    const float* __restrict__ A0, const float* __restrict__ A1, int splitTiles,
    const float* __restrict__ W, const float* __restrict__ bias,
    float* __restrict__ C, int N, int K)
{
    __shared__ float As[BKK][BM];
    __shared__ float Bs[BKK][BN + 4];

    int tid = threadIdx.x;
    int bx = blockIdx.x, by = blockIdx.y;

    const float* A = (by < splitTiles)
        ? A0 + (size_t)by * BM * K
        : A1 + (size_t)(by - splitTiles) * BM * K;
    const float* Wp = W + (size_t)bx * BN * K;

    int arow  = tid >> 2;       // 0..63
    int acol4 = tid & 3;        // 0..3 (float4 within the 16-wide k-slab)
    int tx = tid & 15, ty = tid >> 4;

    float acc[TM][TN];
#pragma unroll
    for (int i = 0; i < TM; i++)
#pragma unroll
        for (int j = 0; j < TN; j++) acc[i][j] = 0.f;

    for (int kt = 0; kt < K; kt += BKK) {
#pragma unroll
        for (int i = 0; i < 2; i++) {
            int r = arow + i * 64;
            float4 a = *(const float4*)(A + (size_t)r * K + kt + acol4 * 4);
            As[acol4 * 4 + 0][r] = a.x;
            As[acol4 * 4 + 1][r] = a.y;
            As[acol4 * 4 + 2][r] = a.z;
            As[acol4 * 4 + 3][r] = a.w;
        }
#pragma unroll
        for (int i = 0; i < 2; i++) {
            int r = arow + i * 64;
            float4 b = *(const float4*)(Wp + (size_t)r * K + kt + acol4 * 4);
            Bs[acol4 * 4 + 0][r] = b.x;
            Bs[acol4 * 4 + 1][r] = b.y;
            Bs[acol4 * 4 + 2][r] = b.z;
            Bs[acol4 * 4 + 3][r] = b.w;
        }
        __syncthreads();

#pragma unroll
        for (int kk = 0; kk < BKK; kk++) {
            float a[TM], b[TN];
            float4 a0 = *(const float4*)&As[kk][ty * TM + 0];
            float4 a1 = *(const float4*)&As[kk][ty * TM + 4];
            a[0]=a0.x; a[1]=a0.y; a[2]=a0.z; a[3]=a0.w;
            a[4]=a1.x; a[5]=a1.y; a[6]=a1.z; a[7]=a1.w;
            float4 b0 = *(const float4*)&Bs[kk][tx * TN + 0];
            float4 b1 = *(const float4*)&Bs[kk][tx * TN + 4];
            b[0]=b0.x; b[1]=b0.y; b[2]=b0.z; b[3]=b0.w;
            b[4]=b1.x; b[5]=b1.y; b[6]=b1.z; b[7]=b1.w;
#pragma unroll
            for (int i = 0; i < TM; i++)
#pragma unroll
                for (int j = 0; j < TN; j++)
                    acc[i][j] += a[i] * b[j];
        }
        __syncthreads();
    }

    int row0 = by * BM + ty * TM;
    int col0 = bx * BN + tx * TN;
    float4 bv0 = *(const float4*)(bias + col0 + 0);
    float4 bv1 = *(const float4*)(bias + col0 + 4);
#pragma unroll
    for (int i = 0; i < TM; i++) {
        size_t base = (size_t)(row0 + i) * N + col0;
        float4 o0, o1;
        o0.x = acc[i][0] + bv0.x; o0.y = acc[i][1] + bv0.y;
        o0.z = acc[i][2] + bv0.z; o0.w = acc[i][3] + bv0.w;
        o1.x = acc[i][4] + bv1.x; o1.y = acc[i][5] + bv1.y;
        o1.z = acc[i][6] + bv1.z; o1.w = acc[i][7] + bv1.w;
        *(float4*)(C + base + 0) = o0;
        *(float4*)(C + base + 4) = o1;
    }
}

// ---------------- kernel 3: attention per (block, head) --------------------
#define STR 68                      // smem row stride in floats
#define ATTN_SMEM ((64 * STR + 65 * STR + 65 * STR) * 4)   // 52768 B

__device__ __forceinline__ float dot64(const float* __restrict__ a,
                                       const float* __restrict__ b) {
    float s = 0.f;
#pragma unroll
    for (int d = 0; d < 64; d += 4) {
        float4 av = *(const float4*)(a + d);
        float4 bv = *(const float4*)(b + d);
        s += av.x * bv.x + av.y * bv.y + av.z * bv.z + av.w * bv.w;
    }
    return s;
}

__global__ __launch_bounds__(256) void attn_kernel(
    const float* __restrict__ edge, const int* __restrict__ mask,
    const float* __restrict__ eg_w, const float* __restrict__ eg_b)
{
    extern __shared__ float sm[];
    float* qs = sm;                  // 64 x STR  (later reused for combined)
    float* ks = sm + 64 * STR;       // 65 x STR
    float* vs = ks + 65 * STR;       // 65 x STR

    int blk = blockIdx.x;            // 0..NBLK-1  (b*NBPB + n)
    int h   = blockIdx.y;
    int tid = threadIdx.x;

    // load q (64x64), k/v (65x64) head slices
    for (int f = tid; f < 64 * 16; f += 256) {
        int r = f >> 4, c = f & 15;
        float4 v = *(const float4*)(g_yqkv + (size_t)(blk * 64 + r) * QKVN + h * 64 + c * 4);
        *(float4*)&qs[r * STR + c * 4] = v;
    }
    for (int f = tid; f < 65 * 16; f += 256) {
        int r = f >> 4, c = f & 15;
        size_t grow = (r < 64) ? (size_t)(blk * 64 + r) : (size_t)(MTOK + blk);
        float4 kv4 = *(const float4*)(g_yqkv + grow * QKVN + DIM + h * 64 + c * 4);
        *(float4*)&ks[r * STR + c * 4] = kv4;
        float4 vv4 = *(const float4*)(g_yqkv + grow * QKVN + 2 * DIM + h * 64 + c * 4);
        *(float4*)&vs[r * STR + c * 4] = vv4;
    }
    __syncthreads();

    int wid = tid >> 5, lane = tid & 31;
    const float scale = 0.125f;      // 64^-0.5
    float w0 = eg_w[h * 4 + 0], w1 = eg_w[h * 4 + 1];
    float w2 = eg_w[h * 4 + 2], w3 = eg_w[h * 4 + 3];
    float bh = eg_b[h];
    size_t mbase = (size_t)blk * 64 * KEYS;

    for (int q = wid * 8; q < wid * 8 + 8; q++) {
        int k1 = lane, k2 = lane + 32;          // k2 in [32,63]
        float s1 = dot64(qs + q * STR, ks + k1 * STR);
        float s2 = dot64(qs + q * STR, ks + k2 * STR);
        float s3 = (lane == 0) ? dot64(qs + q * STR, ks + 64 * STR) : 0.f;

        const int*   mrow = mask + mbase + (size_t)q * KEYS;
        const float* erow = edge + (mbase + (size_t)q * KEYS) * 4;

        // key k1
        int m1 = mrow[k1];
        float b1, l1;
        if (k1 == q) { b1 = 1.f; l1 = w3 + bh; }
        else {
            float4 e = *(const float4*)(erow + k1 * 4);
            b1 = e.w; l1 = e.x * w0 + e.y * w1 + e.z * w2 + e.w * w3 + bh;
        }
        s1 = s1 * scale + b1; if (m1 == 0) { s1 = -1e30f; l1 = 0.f; }

        // key k2
        int m2 = mrow[k2];
        float b2, l2;
        if (k2 == q) { b2 = 1.f; l2 = w3 + bh; }
        else {
            float4 e = *(const float4*)(erow + k2 * 4);
            b2 = e.w; l2 = e.x * w0 + e.y * w1 + e.z * w2 + e.w * w3 + bh;
        }
        s2 = s2 * scale + b2; if (m2 == 0) { s2 = -1e30f; l2 = 0.f; }

        // key 64 (block node; always unmasked, bias=(0,0,0,1))
        float l3 = w3 + bh;
        s3 = s3 * scale + 1.f;

        float mx = fmaxf(s1, s2);
        if (lane == 0) mx = fmaxf(mx, s3);
#pragma unroll
        for (int o = 16; o; o >>= 1) mx = fmaxf(mx, __shfl_xor_sync(0xffffffffu, mx, o));

        float e1 = expf(s1 - mx);
        float e2 = expf(s2 - mx);
        float e3 = (lane == 0) ? expf(s3 - mx) : 0.f;
        float sum = e1 + e2 + e3;
#pragma unroll
        for (int o = 16; o; o >>= 1) sum += __shfl_xor_sync(0xffffffffu, sum, o);
        float inv = 1.f / sum;

        float c1 = e1 * inv + l1;
        float c2 = e2 * inv + l2;
        float c3 = e3 * inv + l3;   // only lane 0's value used

        __syncwarp();               // all q-row reads done before overwrite
        qs[q * STR + k1] = c1;
        qs[q * STR + k2] = c2;
        if (lane == 0) qs[q * STR + 64] = c3;
        __syncwarp();
    }
    __syncthreads();

    // out[q, d] = sum_k combined[q,k] * v[k,d]
    for (int q = wid * 8; q < wid * 8 + 8; q++) {
        const float* crow = qs + q * STR;
        float2 acc = make_float2(0.f, 0.f);
        for (int k = 0; k < 65; k++) {
            float c = crow[k];
            float2 vv = *(const float2*)(vs + k * STR + lane * 2);
            acc.x += c * vv.x; acc.y += c * vv.y;
        }
        *(float2*)(g_attnout + (size_t)(blk * 64 + q) * DIM + h * 64 + lane * 2) = acc;
    }
}

// ---------------- host ------------------------------------------------------
extern "C" void kernel_launch(void* const* d_in, const int* in_sizes, int n_in,
                              void* d_out, int out_size)
{
    const float* x      = (const float*)d_in[0];
    const int*   mask   = (const int*)  d_in[1];
    const float* edge   = (const float*)d_in[2];
    const float* qkv_w  = (const float*)d_in[3];
    const float* qkv_b  = (const float*)d_in[4];
    const float* proj_w = (const float*)d_in[5];
    const float* proj_b = (const float*)d_in[6];
    const float* eg_w   = (const float*)d_in[7];
    const float* eg_b   = (const float*)d_in[8];
    float* out = (float*)d_out;

    void *p_bn, *p_yqkv, *p_ao;
    cudaGetSymbolAddress(&p_bn,   g_blocknode);
    cudaGetSymbolAddress(&p_yqkv, g_yqkv);
    cudaGetSymbolAddress(&p_ao,   g_attnout);
    float* bn   = (float*)p_bn;
    float* yqkv = (float*)p_yqkv;
    float* ao   = (float*)p_ao;

    // 1. block means
    block_mean_kernel<<<NBLK, 128>>>(x);

    // 2. fused QKV GEMM over tokens + block nodes
    dim3 g1(QKVN / BN, MAUG / BM);            // (12, 520)
    sgemm_bias_kernel<<<g1, 256>>>(x, bn, MTOK / BM, qkv_w, qkv_b, yqkv, QKVN, DIM);

    // 3. attention
    cudaFuncSetAttribute(attn_kernel, cudaFuncAttributeMaxDynamicSharedMemorySize, ATTN_SMEM);
    dim3 g2(NBLK, NHEAD);                     // (1024, 8)
    attn_kernel<<<g2, 256, ATTN_SMEM>>>(edge, mask, eg_w, eg_b);

    // 4. output projection
    dim3 g3(DIM / BN, MTOK / BM);             // (4, 512)
    sgemm_bias_kernel<<<g3, 256>>>(ao, ao, 1 << 30, proj_w, proj_b, out, DIM, DIM);
}

// round 3
// speedup vs baseline: 1.6740x; 1.6740x over previous
#include <cuda_runtime.h>
#include <cuda_bf16.h>
#include <cstdint>
#include <math.h>

#define DIM   512
#define LBLK  64
#define NHEAD 8
#define HDIM  64
#define KEYS  65
#define BB    2
#define NTOK  32768
#define NBPB  512
#define NBLK  (BB*NBPB)           // 1024
#define MTOK  (BB*NTOK)           // 65536
#define MAUG  (MTOK+NBLK)         // 66560
#define QKVN  (3*DIM)             // 1536
#define GK    512

// ---------------- scratch (device globals; no runtime allocation) ----------
__device__ __nv_bfloat16 g_xh[(size_t)MAUG * DIM];
__device__ __nv_bfloat16 g_xl[(size_t)MAUG * DIM];
__device__ float         g_yqkv[(size_t)MAUG * QKVN];
__device__ __nv_bfloat16 g_aoh[(size_t)MTOK * DIM];
__device__ __nv_bfloat16 g_aol[(size_t)MTOK * DIM];
__device__ __nv_bfloat16 g_qwh[(size_t)QKVN * DIM];
__device__ __nv_bfloat16 g_qwl[(size_t)QKVN * DIM];
__device__ __nv_bfloat16 g_pwh[(size_t)DIM * DIM];
__device__ __nv_bfloat16 g_pwl[(size_t)DIM * DIM];

// ---------------- helpers ---------------------------------------------------
__device__ __forceinline__ uint32_t smem_u32(const void* p) {
    uint32_t a;
    asm("{ .reg .u64 t; cvta.to.shared.u64 t, %1; cvt.u32.u64 %0, t; }"
        : "=r"(a) : "l"(p));
    return a;
}
__device__ __forceinline__ void cp_async16(uint32_t dst, const void* src) {
    asm volatile("cp.async.cg.shared.global [%0], [%1], 16;"
                 :: "r"(dst), "l"(src) : "memory");
}
#define CP_COMMIT() asm volatile("cp.async.commit_group;" ::: "memory")
#define CP_WAIT(n)  asm volatile("cp.async.wait_group %0;" :: "n"(n) : "memory")

__device__ __forceinline__ void ldsm4(uint32_t (&r)[4], uint32_t addr) {
    asm volatile("ldmatrix.sync.aligned.m8n8.x4.shared.b16 {%0,%1,%2,%3}, [%4];"
                 : "=r"(r[0]), "=r"(r[1]), "=r"(r[2]), "=r"(r[3]) : "r"(addr));
}
__device__ __forceinline__ void mma16816(float (&d)[4], const uint32_t (&a)[4],
                                         const uint32_t b0, const uint32_t b1) {
    asm volatile(
        "mma.sync.aligned.m16n8k16.row.col.f32.bf16.bf16.f32 "
        "{%0,%1,%2,%3}, {%4,%5,%6,%7}, {%8,%9}, {%0,%1,%2,%3};"
        : "+f"(d[0]), "+f"(d[1]), "+f"(d[2]), "+f"(d[3])
        : "r"(a[0]), "r"(a[1]), "r"(a[2]), "r"(a[3]), "r"(b0), "r"(b1));
}

__device__ __forceinline__ void split1(float v, __nv_bfloat16& h, __nv_bfloat16& l) {
    h = __float2bfloat16(v);
    l = __float2bfloat16(v - __bfloat162float(h));
}

// ---------------- fp32 -> bf16 hi/lo ----------------------------------------
__global__ void convert_split_kernel(const float* __restrict__ src,
                                     __nv_bfloat16* __restrict__ hi,
                                     __nv_bfloat16* __restrict__ lo, int n4) {
    int i = blockIdx.x * blockDim.x + threadIdx.x;
    if (i >= n4) return;
    float4 v = ((const float4*)src)[i];
    __nv_bfloat16 h0, h1, h2, h3, l0, l1, l2, l3;
    split1(v.x, h0, l0); split1(v.y, h1, l1);
    split1(v.z, h2, l2); split1(v.w, h3, l3);
    ((__nv_bfloat162*)hi)[2 * i]     = __nv_bfloat162{h0, h1};
    ((__nv_bfloat162*)hi)[2 * i + 1] = __nv_bfloat162{h2, h3};
    ((__nv_bfloat162*)lo)[2 * i]     = __nv_bfloat162{l0, l1};
    ((__nv_bfloat162*)lo)[2 * i + 1] = __nv_bfloat162{l2, l3};
}

// ---------------- block mean -> bf16 hi/lo at row MTOK+blk ------------------
__global__ void block_mean_kernel(const float* __restrict__ x) {
    int blk = blockIdx.x;
    int c4  = threadIdx.x;
    const float4* xr = (const float4*)x + (size_t)blk * LBLK * (DIM / 4) + c4;
    float4 acc = make_float4(0.f, 0.f, 0.f, 0.f);
#pragma unroll 4
    for (int r = 0; r < LBLK; r++) {
        float4 v = xr[(size_t)r * (DIM / 4)];
        acc.x += v.x; acc.y += v.y; acc.z += v.z; acc.w += v.w;
    }
    const float s = 1.f / 64.f;
    acc.x *= s; acc.y *= s; acc.z *= s; acc.w *= s;
    __nv_bfloat16 h0, h1, h2, h3, l0, l1, l2, l3;
    split1(acc.x, h0, l0); split1(acc.y, h1, l1);
    split1(acc.z, h2, l2); split1(acc.w, h3, l3);
    size_t base = ((size_t)(MTOK + blk) * DIM) / 2 + c4 * 2;
    ((__nv_bfloat162*)g_xh)[base]     = __nv_bfloat162{h0, h1};
    ((__nv_bfloat162*)g_xh)[base + 1] = __nv_bfloat162{h2, h3};
    ((__nv_bfloat162*)g_xl)[base]     = __nv_bfloat162{l0, l1};
    ((__nv_bfloat162*)g_xl)[base + 1] = __nv_bfloat162{l2, l3};
}

// ---------------- HMMA split-bf16 GEMM: C[M,N] = A@W^T + bias ---------------
// 128x128 tile/CTA, BK=32 double-buffered cp.async, 8 warps (4m x 2n, 32x64).
// smem arrays (per buffer): Ah, Al, Bh, Bl each 128 rows x 40 bf16 (80B rows).
#define SROW 40                      // bf16 per smem row (32 data + 8 pad)
#define ATILE (128 * SROW * 2)       // 10240 B
#define BUFSZ (4 * ATILE)            // 40960 B
#define GEMM_SMEM (2 * BUFSZ)        // 81920 B

__global__ __launch_bounds__(256, 1) void gemm_hmma_split(
    const __nv_bfloat16* __restrict__ Ah, const __nv_bfloat16* __restrict__ Al,
    const __nv_bfloat16* __restrict__ Wh, const __nv_bfloat16* __restrict__ Wl,
    const float* __restrict__ bias, float* __restrict__ C, int Nout)
{
    extern __shared__ char smc[];
    const uint32_t sbase = smem_u32(smc);
    const int tid = threadIdx.x, wid = tid >> 5, lane = tid & 31;
    const int tN = blockIdx.x, tM = blockIdx.y;
    const int wm = wid & 3, wn = wid >> 2;          // warp tile (32m x 64n)

    const size_t arow0 = (size_t)tM * 128;
    const size_t wrow0 = (size_t)tN * 128;
    const __nv_bfloat16* srcs[4] = {Ah, Al, Wh, Wl};

    // loader assignment: per array, thread handles chunks tid and tid+256
    // chunk c: row = c>>2, q = c&3  (16B = 8 bf16 per chunk)
    auto load_slab = [&](int s, int buf) {
        uint32_t sb = sbase + buf * BUFSZ;
#pragma unroll
        for (int a = 0; a < 4; a++) {
            const __nv_bfloat16* src = srcs[a] + ((a < 2) ? arow0 : wrow0) * GK + s * 32;
#pragma unroll
            for (int i = 0; i < 2; i++) {
                int c = tid + 256 * i;
                int row = c >> 2, q = c & 3;
                cp_async16(sb + a * ATILE + row * (SROW * 2) + q * 16,
                           src + (size_t)row * GK + q * 8);
            }
        }
        CP_COMMIT();
    };

    float acc[2][8][4];
#pragma unroll
    for (int mi = 0; mi < 2; mi++)
#pragma unroll
        for (int ni = 0; ni < 8; ni++)
#pragma unroll
            for (int j = 0; j < 4; j++) acc[mi][ni][j] = 0.f;

    // ldmatrix per-thread row/k selects
    const int a_row = lane & 15, a_kq = lane >> 4;            // A: x4 over m16k16
    const int b_row = (lane & 7) + ((lane >> 4) << 3);        // B: x4 over n16k16
    const int b_kh = (lane >> 3) & 1;

    load_slab(0, 0);
    for (int s = 0; s < 16; s++) {
        if (s + 1 < 16) { load_slab(s + 1, (s + 1) & 1); CP_WAIT(1); }
        else            { CP_WAIT(0); }
        __syncthreads();

        const uint32_t sb = sbase + (s & 1) * BUFSZ;
#pragma unroll
        for (int kk = 0; kk < 2; kk++) {
            uint32_t af[2][2][4];                 // [h/l][mi][4]
#pragma unroll
            for (int p = 0; p < 2; p++)
#pragma unroll
                for (int mi = 0; mi < 2; mi++) {
                    uint32_t addr = sb + p * ATILE +
                        (wm * 32 + mi * 16 + a_row) * (SROW * 2) +
                        (kk * 16 + a_kq * 8) * 2;
                    ldsm4(af[p][mi], addr);
                }
            uint32_t bf[2][8][2];                 // [h/l][ni][2]
#pragma unroll
            for (int p = 0; p < 2; p++)
#pragma unroll
                for (int j = 0; j < 4; j++) {
                    uint32_t addr = sb + (2 + p) * ATILE +
                        (wn * 64 + j * 16 + b_row) * (SROW * 2) +
                        (kk * 16 + b_kh * 8) * 2;
                    uint32_t r[4];
                    ldsm4(r, addr);
                    bf[p][2 * j][0] = r[0]; bf[p][2 * j][1] = r[1];
                    bf[p][2 * j + 1][0] = r[2]; bf[p][2 * j + 1][1] = r[3];
                }
#pragma unroll
            for (int mi = 0; mi < 2; mi++)
#pragma unroll
                for (int ni = 0; ni < 8; ni++) {
                    mma16816(acc[mi][ni], af[0][mi], bf[0][ni][0], bf[0][ni][1]);
                    mma16816(acc[mi][ni], af[0][mi], bf[1][ni][0], bf[1][ni][1]);
                    mma16816(acc[mi][ni], af[1][mi], bf[0][ni][0], bf[0][ni][1]);
                }
        }
        __syncthreads();
    }

    // epilogue: acc frag (t/4 = row-in-8, (t%4)*2 = col pair)
    const int r4 = lane >> 2, c2 = (lane & 3) * 2;
#pragma unroll
    for (int mi = 0; mi < 2; mi++) {
        int row = tM * 128 + wm * 32 + mi * 16 + r4;
#pragma unroll
        for (int ni = 0; ni < 8; ni++) {
            int col = tN * 128 + wn * 64 + ni * 8 + c2;
            float2 bv = *(const float2*)(bias + col);
            float2 o0, o1;
            o0.x = acc[mi][ni][0] + bv.x; o0.y = acc[mi][ni][1] + bv.y;
            o1.x = acc[mi][ni][2] + bv.x; o1.y = acc[mi][ni][3] + bv.y;
            *(float2*)(C + (size_t)row * Nout + col) = o0;
            *(float2*)(C + (size_t)(row + 8) * Nout + col) = o1;
        }
    }
}

// ---------------- attention per (block, head) -------------------------------
#define STR 68
#define ATTN_SMEM ((64 * STR + 65 * STR + 65 * STR) * 4)

__device__ __forceinline__ float dot64(const float* __restrict__ a,
                                       const float* __restrict__ b) {
    float s = 0.f;
#pragma unroll
    for (int d = 0; d < 64; d += 4) {
        float4 av = *(const float4*)(a + d);
        float4 bv = *(const float4*)(b + d);
        s += av.x * bv.x + av.y * bv.y + av.z * bv.z + av.w * bv.w;
    }
    return s;
}

__global__ __launch_bounds__(256) void attn_kernel(
    const float* __restrict__ edge, const int* __restrict__ mask,
    const float* __restrict__ eg_w, const float* __restrict__ eg_b)
{
    extern __shared__ float smf[];
    float* qs = smf;
    float* ks = smf + 64 * STR;
    float* vs = ks + 65 * STR;

    int blk = blockIdx.x;
    int h   = blockIdx.y;
    int tid = threadIdx.x;

    for (int f = tid; f < 64 * 16; f += 256) {
        int r = f >> 4, c = f & 15;
        float4 v = *(const float4*)(g_yqkv + (size_t)(blk * 64 + r) * QKVN + h * 64 + c * 4);
        *(float4*)&qs[r * STR + c * 4] = v;
    }
    for (int f = tid; f < 65 * 16; f += 256) {
        int r = f >> 4, c = f & 15;
        size_t grow = (r < 64) ? (size_t)(blk * 64 + r) : (size_t)(MTOK + blk);
        float4 kv4 = *(const float4*)(g_yqkv + grow * QKVN + DIM + h * 64 + c * 4);
        *(float4*)&ks[r * STR + c * 4] = kv4;
        float4 vv4 = *(const float4*)(g_yqkv + grow * QKVN + 2 * DIM + h * 64 + c * 4);
        *(float4*)&vs[r * STR + c * 4] = vv4;
    }
    __syncthreads();

    int wid = tid >> 5, lane = tid & 31;
    const float scale = 0.125f;
    float w0 = eg_w[h * 4 + 0], w1 = eg_w[h * 4 + 1];
    float w2 = eg_w[h * 4 + 2], w3 = eg_w[h * 4 + 3];
    float bh = eg_b[h];
    size_t mbase = (size_t)blk * 64 * KEYS;

    for (int q = wid * 8; q < wid * 8 + 8; q++) {
        int k1 = lane, k2 = lane + 32;
        float s1 = dot64(qs + q * STR, ks + k1 * STR);
        float s2 = dot64(qs + q * STR, ks + k2 * STR);
        float s3 = (lane == 0) ? dot64(qs + q * STR, ks + 64 * STR) : 0.f;

        const int*   mrow = mask + mbase + (size_t)q * KEYS;
        const float* erow = edge + (mbase + (size_t)q * KEYS) * 4;

        int m1 = mrow[k1];
        float b1, l1;
        if (k1 == q) { b1 = 1.f; l1 = w3 + bh; }
        else {
            float4 e = *(const float4*)(erow + k1 * 4);
            b1 = e.w; l1 = e.x * w0 + e.y * w1 + e.z * w2 + e.w * w3 + bh;
        }
        s1 = s1 * scale + b1; if (m1 == 0) { s1 = -1e30f; l1 = 0.f; }

        int m2 = mrow[k2];
        float b2, l2;
        if (k2 == q) { b2 = 1.f; l2 = w3 + bh; }
        else {
            float4 e = *(const float4*)(erow + k2 * 4);
            b2 = e.w; l2 = e.x * w0 + e.y * w1 + e.z * w2 + e.w * w3 + bh;
        }
        s2 = s2 * scale + b2; if (m2 == 0) { s2 = -1e30f; l2 = 0.f; }

        float l3 = w3 + bh;
        s3 = s3 * scale + 1.f;

        float mx = fmaxf(s1, s2);
        if (lane == 0) mx = fmaxf(mx, s3);
#pragma unroll
        for (int o = 16; o; o >>= 1) mx = fmaxf(mx, __shfl_xor_sync(0xffffffffu, mx, o));

        float e1 = expf(s1 - mx);
        float e2 = expf(s2 - mx);
        float e3 = (lane == 0) ? expf(s3 - mx) : 0.f;
        float sum = e1 + e2 + e3;
#pragma unroll
        for (int o = 16; o; o >>= 1) sum += __shfl_xor_sync(0xffffffffu, sum, o);
        float inv = 1.f / sum;

        float c1 = e1 * inv + l1;
        float c2 = e2 * inv + l2;
        float c3 = e3 * inv + l3;

        __syncwarp();
        qs[q * STR + k1] = c1;
        qs[q * STR + k2] = c2;
        if (lane == 0) qs[q * STR + 64] = c3;
        __syncwarp();
    }
    __syncthreads();

    for (int q = wid * 8; q < wid * 8 + 8; q++) {
        const float* crow = qs + q * STR;
        float2 acc = make_float2(0.f, 0.f);
        for (int k = 0; k < 65; k++) {
            float c = crow[k];
            float2 vv = *(const float2*)(vs + k * STR + lane * 2);
            acc.x += c * vv.x; acc.y += c * vv.y;
        }
        __nv_bfloat16 hx, lx, hy, ly;
        split1(acc.x, hx, lx); split1(acc.y, hy, ly);
        size_t idx = ((size_t)(blk * 64 + q) * DIM + h * 64 + lane * 2) / 2;
        ((__nv_bfloat162*)g_aoh)[idx] = __nv_bfloat162{hx, hy};
        ((__nv_bfloat162*)g_aol)[idx] = __nv_bfloat162{lx, ly};
    }
}

// ---------------- host ------------------------------------------------------
extern "C" void kernel_launch(void* const* d_in, const int* in_sizes, int n_in,
                              void* d_out, int out_size)
{
    const float* x      = (const float*)d_in[0];
    const int*   mask   = (const int*)  d_in[1];
    const float* edge   = (const float*)d_in[2];
    const float* qkv_w  = (const float*)d_in[3];
    const float* qkv_b  = (const float*)d_in[4];
    const float* proj_w = (const float*)d_in[5];
    const float* proj_b = (const float*)d_in[6];
    const float* eg_w   = (const float*)d_in[7];
    const float* eg_b   = (const float*)d_in[8];
    float* out = (float*)d_out;

    void *p_xh, *p_xl, *p_yqkv, *p_aoh, *p_aol, *p_qwh, *p_qwl, *p_pwh, *p_pwl;
    cudaGetSymbolAddress(&p_xh, g_xh);   cudaGetSymbolAddress(&p_xl, g_xl);
    cudaGetSymbolAddress(&p_yqkv, g_yqkv);
    cudaGetSymbolAddress(&p_aoh, g_aoh); cudaGetSymbolAddress(&p_aol, g_aol);
    cudaGetSymbolAddress(&p_qwh, g_qwh); cudaGetSymbolAddress(&p_qwl, g_qwl);
    cudaGetSymbolAddress(&p_pwh, g_pwh); cudaGetSymbolAddress(&p_pwl, g_pwl);

    cudaFuncSetAttribute(gemm_hmma_split, cudaFuncAttributeMaxDynamicSharedMemorySize, GEMM_SMEM);
    cudaFuncSetAttribute(attn_kernel, cudaFuncAttributeMaxDynamicSharedMemorySize, ATTN_SMEM);

    // 1. conversions + block means
    convert_split_kernel<<<(MTOK * DIM / 4 + 255) / 256, 256>>>(
        x, (__nv_bfloat16*)p_xh, (__nv_bfloat16*)p_xl, MTOK * DIM / 4);
    convert_split_kernel<<<(QKVN * DIM / 4 + 255) / 256, 256>>>(
        qkv_w, (__nv_bfloat16*)p_qwh, (__nv_bfloat16*)p_qwl, QKVN * DIM / 4);
    convert_split_kernel<<<(DIM * DIM / 4 + 255) / 256, 256>>>(
        proj_w, (__nv_bfloat16*)p_pwh, (__nv_bfloat16*)p_pwl, DIM * DIM / 4);
    block_mean_kernel<<<NBLK, 128>>>(x);

    // 2. QKV GEMM (tokens + block nodes)
    dim3 g1(QKVN / 128, MAUG / 128);          // (12, 520)
    gemm_hmma_split<<<g1, 256, GEMM_SMEM>>>(
        (const __nv_bfloat16*)p_xh, (const __nv_bfloat16*)p_xl,
        (const __nv_bfloat16*)p_qwh, (const __nv_bfloat16*)p_qwl,
        qkv_b, (float*)p_yqkv, QKVN);

    // 3. attention
    dim3 g2(NBLK, NHEAD);
    attn_kernel<<<g2, 256, ATTN_SMEM>>>(edge, mask, eg_w, eg_b);

    // 4. output projection
    dim3 g3(DIM / 128, MTOK / 128);           // (4, 512)
    gemm_hmma_split<<<g3, 256, GEMM_SMEM>>>(
        (const __nv_bfloat16*)p_aoh, (const __nv_bfloat16*)p_aol,
        (const __nv_bfloat16*)p_pwh, (const __nv_bfloat16*)p_pwl,
        proj_b, out, DIM);
}

// round 4
// speedup vs baseline: 2.2837x; 1.3642x over previous
#include <cuda_runtime.h>
#include <cuda_bf16.h>
#include <cstdint>
#include <math.h>

#define DIM   512
#define LBLK  64
#define NHEAD 8
#define KEYS  65
#define BB    2
#define NTOK  32768
#define NBPB  512
#define NBLK  (BB*NBPB)           // 1024
#define MTOK  (BB*NTOK)           // 65536
#define MAUG  (MTOK+NBLK)         // 66560
#define QKVN  (3*DIM)             // 1536
#define GK    512

// ---------------- scratch ----------------------------------------------------
__device__ __nv_bfloat16 g_xh[(size_t)MAUG * DIM];
__device__ __nv_bfloat16 g_xl[(size_t)MAUG * DIM];
__device__ float         g_yqkv[(size_t)MAUG * QKVN];
__device__ __nv_bfloat16 g_aoh[(size_t)MTOK * DIM];
__device__ __nv_bfloat16 g_aol[(size_t)MTOK * DIM];
__device__ __nv_bfloat16 g_qwh[(size_t)QKVN * DIM];
__device__ __nv_bfloat16 g_qwl[(size_t)QKVN * DIM];
__device__ __nv_bfloat16 g_pwh[(size_t)DIM * DIM];
__device__ __nv_bfloat16 g_pwl[(size_t)DIM * DIM];

// ---------------- helpers ----------------------------------------------------
__device__ __forceinline__ uint32_t smem_u32(const void* p) {
    uint32_t a;
    asm("{ .reg .u64 t; cvta.to.shared.u64 t, %1; cvt.u32.u64 %0, t; }"
        : "=r"(a) : "l"(p));
    return a;
}
__device__ __forceinline__ void cp_async16(uint32_t dst, const void* src) {
    asm volatile("cp.async.cg.shared.global [%0], [%1], 16;"
                 :: "r"(dst), "l"(src) : "memory");
}
#define CP_COMMIT() asm volatile("cp.async.commit_group;" ::: "memory")
#define CP_WAIT(n)  asm volatile("cp.async.wait_group %0;" :: "n"(n) : "memory")

__device__ __forceinline__ void ldsm4(uint32_t (&r)[4], uint32_t addr) {
    asm volatile("ldmatrix.sync.aligned.m8n8.x4.shared.b16 {%0,%1,%2,%3}, [%4];"
                 : "=r"(r[0]), "=r"(r[1]), "=r"(r[2]), "=r"(r[3]) : "r"(addr));
}
__device__ __forceinline__ void mma16816(float (&d)[4], const uint32_t (&a)[4],
                                         const uint32_t b0, const uint32_t b1) {
    asm volatile(
        "mma.sync.aligned.m16n8k16.row.col.f32.bf16.bf16.f32 "
        "{%0,%1,%2,%3}, {%4,%5,%6,%7}, {%8,%9}, {%0,%1,%2,%3};"
        : "+f"(d[0]), "+f"(d[1]), "+f"(d[2]), "+f"(d[3])
        : "r"(a[0]), "r"(a[1]), "r"(a[2]), "r"(a[3]), "r"(b0), "r"(b1));
}
__device__ __forceinline__ void split1(float v, __nv_bfloat16& h, __nv_bfloat16& l) {
    h = __float2bfloat16(v);
    l = __float2bfloat16(v - __bfloat162float(h));
}
// pack (c0 -> low, c1 -> high) bf16x2
__device__ __forceinline__ uint32_t pack_bf2(float c0, float c1) {
    uint32_t d;
    asm("cvt.rn.bf16x2.f32 %0, %1, %2;" : "=r"(d) : "f"(c1), "f"(c0));
    return d;
}
__device__ __forceinline__ void packsplit2(float c0, float c1,
                                           uint32_t& hi, uint32_t& lo) {
    hi = pack_bf2(c0, c1);
    float h0 = __uint_as_float(hi << 16);
    float h1 = __uint_as_float(hi & 0xffff0000u);
    lo = pack_bf2(c0 - h0, c1 - h1);
}

// ---------------- fp32 -> bf16 hi/lo -----------------------------------------
__global__ void convert_split_kernel(const float* __restrict__ src,
                                     __nv_bfloat16* __restrict__ hi,
                                     __nv_bfloat16* __restrict__ lo, int n4) {
    int i = blockIdx.x * blockDim.x + threadIdx.x;
    if (i >= n4) return;
    float4 v = ((const float4*)src)[i];
    __nv_bfloat16 h0, h1, h2, h3, l0, l1, l2, l3;
    split1(v.x, h0, l0); split1(v.y, h1, l1);
    split1(v.z, h2, l2); split1(v.w, h3, l3);
    ((__nv_bfloat162*)hi)[2 * i]     = __nv_bfloat162{h0, h1};
    ((__nv_bfloat162*)hi)[2 * i + 1] = __nv_bfloat162{h2, h3};
    ((__nv_bfloat162*)lo)[2 * i]     = __nv_bfloat162{l0, l1};
    ((__nv_bfloat162*)lo)[2 * i + 1] = __nv_bfloat162{l2, l3};
}

// ---------------- block mean -> bf16 hi/lo at row MTOK+blk -------------------
__global__ void block_mean_kernel(const float* __restrict__ x) {
    int blk = blockIdx.x;
    int c4  = threadIdx.x;
    const float4* xr = (const float4*)x + (size_t)blk * LBLK * (DIM / 4) + c4;
    float4 acc = make_float4(0.f, 0.f, 0.f, 0.f);
#pragma unroll 4
    for (int r = 0; r < LBLK; r++) {
        float4 v = xr[(size_t)r * (DIM / 4)];
        acc.x += v.x; acc.y += v.y; acc.z += v.z; acc.w += v.w;
    }
    const float s = 1.f / 64.f;
    acc.x *= s; acc.y *= s; acc.z *= s; acc.w *= s;
    __nv_bfloat16 h0, h1, h2, h3, l0, l1, l2, l3;
    split1(acc.x, h0, l0); split1(acc.y, h1, l1);
    split1(acc.z, h2, l2); split1(acc.w, h3, l3);
    size_t base = ((size_t)(MTOK + blk) * DIM) / 2 + c4 * 2;
    ((__nv_bfloat162*)g_xh)[base]     = __nv_bfloat162{h0, h1};
    ((__nv_bfloat162*)g_xh)[base + 1] = __nv_bfloat162{h2, h3};
    ((__nv_bfloat162*)g_xl)[base]     = __nv_bfloat162{l0, l1};
    ((__nv_bfloat162*)g_xl)[base + 1] = __nv_bfloat162{l2, l3};
}

// ---------------- HMMA split-bf16 GEMM: 128x256 tile, 512 threads ------------
#define SROW 40
#define A_BYTES (128 * SROW * 2)            // 10240
#define B_BYTES (256 * SROW * 2)            // 20480
#define BUFSZ (2 * A_BYTES + 2 * B_BYTES)   // 61440
#define GEMM_SMEM (2 * BUFSZ)               // 122880

__global__ __launch_bounds__(512, 1) void gemm_hmma_split(
    const __nv_bfloat16* __restrict__ Ah, const __nv_bfloat16* __restrict__ Al,
    const __nv_bfloat16* __restrict__ Wh, const __nv_bfloat16* __restrict__ Wl,
    const float* __restrict__ bias, float* __restrict__ C, int Nout)
{
    extern __shared__ char smc[];
    const uint32_t sbase = smem_u32(smc);
    const int tid = threadIdx.x, wid = tid >> 5, lane = tid & 31;
    const int tN = blockIdx.x, tM = blockIdx.y;
    const int wm = wid & 3, wn = wid >> 2;          // 4m x 4n, warp 32x64

    const size_t arow0 = (size_t)tM * 128;
    const size_t wrow0 = (size_t)tN * 256;

    auto load_slab = [&](int s, int buf) {
        uint32_t sb = sbase + buf * BUFSZ;
        {
            int row = tid >> 2, q = tid & 3;       // 512 chunks
            cp_async16(sb + row * (SROW * 2) + q * 16,
                       Ah + (arow0 + row) * GK + s * 32 + q * 8);
            cp_async16(sb + A_BYTES + row * (SROW * 2) + q * 16,
                       Al + (arow0 + row) * GK + s * 32 + q * 8);
        }
#pragma unroll
        for (int i = 0; i < 2; i++) {
            int c = tid + 512 * i;                  // 1024 chunks
            int row = c >> 2, q = c & 3;
            cp_async16(sb + 2 * A_BYTES + row * (SROW * 2) + q * 16,
                       Wh + (wrow0 + row) * GK + s * 32 + q * 8);
            cp_async16(sb + 2 * A_BYTES + B_BYTES + row * (SROW * 2) + q * 16,
                       Wl + (wrow0 + row) * GK + s * 32 + q * 8);
        }
        CP_COMMIT();
    };

    float acc[2][8][4];
#pragma unroll
    for (int mi = 0; mi < 2; mi++)
#pragma unroll
        for (int ni = 0; ni < 8; ni++)
#pragma unroll
            for (int j = 0; j < 4; j++) acc[mi][ni][j] = 0.f;

    const int a_row = lane & 15, a_kq = lane >> 4;
    const int b_row = (lane & 7) + ((lane >> 4) << 3);
    const int b_kh = (lane >> 3) & 1;

    load_slab(0, 0);
    for (int s = 0; s < 16; s++) {
        if (s + 1 < 16) { load_slab(s + 1, (s + 1) & 1); CP_WAIT(1); }
        else            { CP_WAIT(0); }
        __syncthreads();

        const uint32_t sb = sbase + (s & 1) * BUFSZ;
#pragma unroll
        for (int kk = 0; kk < 2; kk++) {
            uint32_t af[2][2][4];
#pragma unroll
            for (int p = 0; p < 2; p++)
#pragma unroll
                for (int mi = 0; mi < 2; mi++) {
                    uint32_t addr = sb + p * A_BYTES +
                        (wm * 32 + mi * 16 + a_row) * (SROW * 2) +
                        (kk * 16 + a_kq * 8) * 2;
                    ldsm4(af[p][mi], addr);
                }
            uint32_t bf[2][8][2];
#pragma unroll
            for (int p = 0; p < 2; p++)
#pragma unroll
                for (int j = 0; j < 4; j++) {
                    uint32_t addr = sb + 2 * A_BYTES + p * B_BYTES +
                        (wn * 64 + j * 16 + b_row) * (SROW * 2) +
                        (kk * 16 + b_kh * 8) * 2;
                    uint32_t r[4];
                    ldsm4(r, addr);
                    bf[p][2 * j][0] = r[0]; bf[p][2 * j][1] = r[1];
                    bf[p][2 * j + 1][0] = r[2]; bf[p][2 * j + 1][1] = r[3];
                }
#pragma unroll
            for (int mi = 0; mi < 2; mi++)
#pragma unroll
                for (int ni = 0; ni < 8; ni++) {
                    mma16816(acc[mi][ni], af[0][mi], bf[0][ni][0], bf[0][ni][1]);
                    mma16816(acc[mi][ni], af[0][mi], bf[1][ni][0], bf[1][ni][1]);
                    mma16816(acc[mi][ni], af[1][mi], bf[0][ni][0], bf[0][ni][1]);
                }
        }
        __syncthreads();
    }

    const int r4 = lane >> 2, c2 = (lane & 3) * 2;
#pragma unroll
    for (int mi = 0; mi < 2; mi++) {
        int row = tM * 128 + wm * 32 + mi * 16 + r4;
#pragma unroll
        for (int ni = 0; ni < 8; ni++) {
            int col = tN * 256 + wn * 64 + ni * 8 + c2;
            float2 bv = *(const float2*)(bias + col);
            float2 o0, o1;
            o0.x = acc[mi][ni][0] + bv.x; o0.y = acc[mi][ni][1] + bv.y;
            o1.x = acc[mi][ni][2] + bv.x; o1.y = acc[mi][ni][3] + bv.y;
            *(float2*)(C + (size_t)row * Nout + col) = o0;
            *(float2*)(C + (size_t)(row + 8) * Nout + col) = o1;
        }
    }
}

// ---------------- HMMA attention per (block, head) ---------------------------
// smem element offsets (bf16): qh[64][72], ql, kh[80][72], kl, vth[64][88], vtl
#define QH_OFF  0
#define QL_OFF  4608
#define KH_OFF  9216
#define KL_OFF  14976
#define VTH_OFF 20736
#define VTL_OFF 26368
#define ATTN_SMEM (32000 * 2)     // 64000 B

__global__ __launch_bounds__(128, 3) void attn_kernel(
    const float* __restrict__ edge, const int* __restrict__ mask,
    const float* __restrict__ eg_w, const float* __restrict__ eg_b)
{
    extern __shared__ __nv_bfloat16 sma[];
    const uint32_t sb32 = smem_u32(sma);
    const int blk = blockIdx.x, h = blockIdx.y;
    const int tid = threadIdx.x, wid = tid >> 5, lane = tid & 31;

    // ---- zero pads: kh/kl rows 65..79, vth/vtl cols 64..79 ----
    for (int i = tid; i < 1080; i += 128) {       // 15 rows * 72
        sma[KH_OFF + 65 * 72 + i] = __nv_bfloat16(0.f);
        sma[KL_OFF + 65 * 72 + i] = __nv_bfloat16(0.f);
    }
    for (int i = tid; i < 512; i += 128) {        // 64 rows * 8 u32 (cols 64..79)
        int r = i >> 3, c = i & 7;
        *(uint32_t*)&sma[VTH_OFF + r * 88 + 64 + c * 2] = 0u;
        *(uint32_t*)&sma[VTL_OFF + r * 88 + 64 + c * 2] = 0u;
    }
    __syncthreads();

    // ---- load q (64 rows), k/v (65 rows incl. block node), split + V transpose
    for (int c = tid; c < 1024; c += 128) {       // q: 64 rows x 16 float4
        int r = c >> 4, c4 = c & 15;
        float4 v = *(const float4*)(g_yqkv + (size_t)(blk * 64 + r) * QKVN + h * 64 + c4 * 4);
        __nv_bfloat16 hh, ll;
#pragma unroll
        for (int e = 0; e < 4; e++) {
            float f = (&v.x)[e];
            split1(f, hh, ll);
            sma[QH_OFF + r * 72 + c4 * 4 + e] = hh;
            sma[QL_OFF + r * 72 + c4 * 4 + e] = ll;
        }
    }
    for (int c = tid; c < 1040; c += 128) {       // k,v: 65 rows x 16 float4
        int r = c >> 4, c4 = c & 15;
        size_t grow = (r < 64) ? (size_t)(blk * 64 + r) : (size_t)(MTOK + blk);
        float4 kv = *(const float4*)(g_yqkv + grow * QKVN + DIM + h * 64 + c4 * 4);
        float4 vv = *(const float4*)(g_yqkv + grow * QKVN + 2 * DIM + h * 64 + c4 * 4);
        __nv_bfloat16 hh, ll;
#pragma unroll
        for (int e = 0; e < 4; e++) {
            split1((&kv.x)[e], hh, ll);
            sma[KH_OFF + r * 72 + c4 * 4 + e] = hh;
            sma[KL_OFF + r * 72 + c4 * 4 + e] = ll;
            split1((&vv.x)[e], hh, ll);
            int d = c4 * 4 + e;
            sma[VTH_OFF + d * 88 + r] = hh;       // transpose: vt[d][key]
            sma[VTL_OFF + d * 88 + r] = ll;
        }
    }
    __syncthreads();

    // ---- QK^T: warp wid owns rows q0..q0+15, all 80 key-cols ----
    const int q0 = wid * 16;
    const int a_row = lane & 15, a_k8 = (lane >> 4) * 8;
    const int b_row = (lane & 7) + ((lane >> 4) << 3);
    const int b_k8 = ((lane >> 3) & 1) * 8;

    float acc[10][4];
#pragma unroll
    for (int j = 0; j < 10; j++)
#pragma unroll
        for (int i = 0; i < 4; i++) acc[j][i] = 0.f;

#pragma unroll
    for (int kt = 0; kt < 4; kt++) {
        uint32_t ah4[4], al4[4];
        ldsm4(ah4, sb32 + (QH_OFF + (q0 + a_row) * 72 + kt * 16 + a_k8) * 2);
        ldsm4(al4, sb32 + (QL_OFF + (q0 + a_row) * 72 + kt * 16 + a_k8) * 2);
#pragma unroll
        for (int t5 = 0; t5 < 5; t5++) {
            uint32_t bh4[4], bl4[4];
            ldsm4(bh4, sb32 + (KH_OFF + (t5 * 16 + b_row) * 72 + kt * 16 + b_k8) * 2);
            ldsm4(bl4, sb32 + (KL_OFF + (t5 * 16 + b_row) * 72 + kt * 16 + b_k8) * 2);
            mma16816(acc[2 * t5],     ah4, bh4[0], bh4[1]);
            mma16816(acc[2 * t5],     ah4, bl4[0], bl4[1]);
            mma16816(acc[2 * t5],     al4, bh4[0], bh4[1]);
            mma16816(acc[2 * t5 + 1], ah4, bh4[2], bh4[3]);
            mma16816(acc[2 * t5 + 1], ah4, bl4[2], bl4[3]);
            mma16816(acc[2 * t5 + 1], al4, bh4[2], bh4[3]);
        }
    }

    // ---- softmax + bias + mask + lew, in fragment registers ----
    const int r4 = lane >> 2, c2b = (lane & 3) * 2;
    const float w0 = eg_w[h * 4 + 0], w1 = eg_w[h * 4 + 1];
    const float w2 = eg_w[h * 4 + 2], w3 = eg_w[h * 4 + 3];
    const float bhh = eg_b[h];
    const float lewd = w3 + bhh;
    const size_t ebase = (size_t)blk * 64 * KEYS;

    uint32_t lewp[10][2];
    float mx0 = -1e30f, mx1 = -1e30f;
#pragma unroll
    for (int j = 0; j < 10; j++) {
#pragma unroll
        for (int half = 0; half < 2; half++) {
            const int q = q0 + r4 + half * 8;
            float lw2[2];
#pragma unroll
            for (int e = 0; e < 2; e++) {
                const int k = j * 8 + c2b + e;
                float s = acc[j][half * 2 + e];
                float sc, lw;
                if (k > 64) { sc = -1e30f; lw = 0.f; }
                else if (k == 64) { sc = s * 0.125f + 1.f; lw = lewd; }
                else {
                    int m = mask[ebase + (size_t)q * KEYS + k];
                    float4 ev = *(const float4*)(edge + (ebase + (size_t)q * KEYS + k) * 4);
                    float b;
                    if (k == q) { b = 1.f; lw = lewd; }
                    else { b = ev.w; lw = ev.x * w0 + ev.y * w1 + ev.z * w2 + ev.w * w3 + bhh; }
                    sc = s * 0.125f + b;
                    if (m == 0) { sc = -1e30f; lw = 0.f; }
                }
                acc[j][half * 2 + e] = sc;
                lw2[e] = lw;
                if (half == 0) mx0 = fmaxf(mx0, sc); else mx1 = fmaxf(mx1, sc);
            }
            lewp[j][half] = pack_bf2(lw2[0], lw2[1]);
        }
    }
    mx0 = fmaxf(mx0, __shfl_xor_sync(0xffffffffu, mx0, 1));
    mx0 = fmaxf(mx0, __shfl_xor_sync(0xffffffffu, mx0, 2));
    mx1 = fmaxf(mx1, __shfl_xor_sync(0xffffffffu, mx1, 1));
    mx1 = fmaxf(mx1, __shfl_xor_sync(0xffffffffu, mx1, 2));

    float sum0 = 0.f, sum1 = 0.f;
#pragma unroll
    for (int j = 0; j < 10; j++) {
        float e0 = __expf(acc[j][0] - mx0); acc[j][0] = e0; sum0 += e0;
        float e1 = __expf(acc[j][1] - mx0); acc[j][1] = e1; sum0 += e1;
        float e2 = __expf(acc[j][2] - mx1); acc[j][2] = e2; sum1 += e2;
        float e3 = __expf(acc[j][3] - mx1); acc[j][3] = e3; sum1 += e3;
    }
    sum0 += __shfl_xor_sync(0xffffffffu, sum0, 1);
    sum0 += __shfl_xor_sync(0xffffffffu, sum0, 2);
    sum1 += __shfl_xor_sync(0xffffffffu, sum1, 1);
    sum1 += __shfl_xor_sync(0xffffffffu, sum1, 2);
    const float inv0 = 1.f / sum0, inv1 = 1.f / sum1;

    // combined -> A fragments (hi/lo) for PV
    uint32_t cah[5][4], cal[5][4];
#pragma unroll
    for (int kt = 0; kt < 5; kt++) {
#pragma unroll
        for (int jj = 0; jj < 2; jj++) {
            const int j = 2 * kt + jj;
#pragma unroll
            for (int half = 0; half < 2; half++) {
                float2 lw;
                lw.x = __uint_as_float(lewp[j][half] << 16);
                lw.y = __uint_as_float(lewp[j][half] & 0xffff0000u);
                const float iv = half ? inv1 : inv0;
                float c0 = acc[j][half * 2 + 0] * iv + lw.x;
                float c1 = acc[j][half * 2 + 1] * iv + lw.y;
                packsplit2(c0, c1, cah[kt][jj * 2 + half], cal[kt][jj * 2 + half]);
            }
        }
    }

    // ---- PV: out[16 x 64] per warp ----
    float out[8][4];
#pragma unroll
    for (int n = 0; n < 8; n++)
#pragma unroll
        for (int i = 0; i < 4; i++) out[n][i] = 0.f;

#pragma unroll
    for (int kt = 0; kt < 5; kt++) {
#pragma unroll
        for (int g = 0; g < 4; g++) {
            uint32_t vh4[4], vl4[4];
            ldsm4(vh4, sb32 + (VTH_OFF + (g * 16 + b_row) * 88 + kt * 16 + b_k8) * 2);
            ldsm4(vl4, sb32 + (VTL_OFF + (g * 16 + b_row) * 88 + kt * 16 + b_k8) * 2);
            mma16816(out[2 * g],     cah[kt], vh4[0], vh4[1]);
            mma16816(out[2 * g],     cah[kt], vl4[0], vl4[1]);
            mma16816(out[2 * g],     cal[kt], vh4[0], vh4[1]);
            mma16816(out[2 * g + 1], cah[kt], vh4[2], vh4[3]);
            mma16816(out[2 * g + 1], cah[kt], vl4[2], vl4[3]);
            mma16816(out[2 * g + 1], cal[kt], vh4[2], vh4[3]);
        }
    }

    // ---- epilogue: write bf16 hi/lo directly ----
#pragma unroll
    for (int n = 0; n < 8; n++) {
        const int d = n * 8 + c2b;
#pragma unroll
        for (int half = 0; half < 2; half++) {
            const int q = q0 + r4 + half * 8;
            const size_t idx = ((size_t)(blk * 64 + q) * DIM + h * 64 + d) / 2;
            uint32_t hi, lo;
            packsplit2(out[n][half * 2], out[n][half * 2 + 1], hi, lo);
            ((uint32_t*)g_aoh)[idx] = hi;
            ((uint32_t*)g_aol)[idx] = lo;
        }
    }
}

// ---------------- host -------------------------------------------------------
extern "C" void kernel_launch(void* const* d_in, const int* in_sizes, int n_in,
                              void* d_out, int out_size)
{
    const float* x      = (const float*)d_in[0];
    const int*   mask   = (const int*)  d_in[1];
    const float* edge   = (const float*)d_in[2];
    const float* qkv_w  = (const float*)d_in[3];
    const float* qkv_b  = (const float*)d_in[4];
    const float* proj_w = (const float*)d_in[5];
    const float* proj_b = (const float*)d_in[6];
    const float* eg_w   = (const float*)d_in[7];
    const float* eg_b   = (const float*)d_in[8];
    float* out = (float*)d_out;

    void *p_xh, *p_xl, *p_yqkv, *p_aoh, *p_aol, *p_qwh, *p_qwl, *p_pwh, *p_pwl;
    cudaGetSymbolAddress(&p_xh, g_xh);   cudaGetSymbolAddress(&p_xl, g_xl);
    cudaGetSymbolAddress(&p_yqkv, g_yqkv);
    cudaGetSymbolAddress(&p_aoh, g_aoh); cudaGetSymbolAddress(&p_aol, g_aol);
    cudaGetSymbolAddress(&p_qwh, g_qwh); cudaGetSymbolAddress(&p_qwl, g_qwl);
    cudaGetSymbolAddress(&p_pwh, g_pwh); cudaGetSymbolAddress(&p_pwl, g_pwl);

    cudaFuncSetAttribute(gemm_hmma_split, cudaFuncAttributeMaxDynamicSharedMemorySize, GEMM_SMEM);
    cudaFuncSetAttribute(attn_kernel, cudaFuncAttributeMaxDynamicSharedMemorySize, ATTN_SMEM);

    convert_split_kernel<<<(MTOK * DIM / 4 + 255) / 256, 256>>>(
        x, (__nv_bfloat16*)p_xh, (__nv_bfloat16*)p_xl, MTOK * DIM / 4);
    convert_split_kernel<<<(QKVN * DIM / 4 + 255) / 256, 256>>>(
        qkv_w, (__nv_bfloat16*)p_qwh, (__nv_bfloat16*)p_qwl, QKVN * DIM / 4);
    convert_split_kernel<<<(DIM * DIM / 4 + 255) / 256, 256>>>(
        proj_w, (__nv_bfloat16*)p_pwh, (__nv_bfloat16*)p_pwl, DIM * DIM / 4);
    block_mean_kernel<<<NBLK, 128>>>(x);

    dim3 g1(QKVN / 256, MAUG / 128);          // (6, 520)
    gemm_hmma_split<<<g1, 512, GEMM_SMEM>>>(
        (const __nv_bfloat16*)p_xh, (const __nv_bfloat16*)p_xl,
        (const __nv_bfloat16*)p_qwh, (const __nv_bfloat16*)p_qwl,
        qkv_b, (float*)p_yqkv, QKVN);

    dim3 g2(NBLK, NHEAD);                     // (1024, 8)
    attn_kernel<<<g2, 128, ATTN_SMEM>>>(edge, mask, eg_w, eg_b);

    dim3 g3(DIM / 256, MTOK / 128);           // (2, 512)
    gemm_hmma_split<<<g3, 512, GEMM_SMEM>>>(
        (const __nv_bfloat16*)p_aoh, (const __nv_bfloat16*)p_aol,
        (const __nv_bfloat16*)p_pwh, (const __nv_bfloat16*)p_pwl,
        proj_b, out, DIM);
}